// round 14
// baseline (speedup 1.0000x reference)
#include <cuda_runtime.h>
#include <math.h>

#define SEQ   16384
#define D4    256           // 1024 floats = 256 float4 per row
#define GRID  296           // 2 blocks/SM on 148 SMs (GB300 has 152 -> headroom)
#define BPH   (GRID / 2)    // 148 blocks per head
#define WPB   8             // warps per block (256 threads)
#define WPH   (BPH * WPB)   // 1184 warps per head

__device__ float g_logits[2 * SEQ];
__device__ float g_blockmax[GRID];
__device__ float g_blocksum[GRID];
__device__ volatile unsigned g_sense; // zero-init; returns to 0 after 2 barriers
__device__ unsigned g_count;          // zero-init; self-resets

// Sense-reversing grid barrier. All GRID blocks must be resident (guaranteed
// by __launch_bounds__(256,2): <=128 regs/thread -> 2 blocks/SM).
// Called an EVEN number of times per launch so g_sense ends at 0 (replay-safe).
__device__ __forceinline__ void grid_barrier(unsigned target)
{
    __threadfence();   // make this thread's prior global writes visible
    __syncthreads();
    if (threadIdx.x == 0) {
        unsigned arrived = atomicAdd(&g_count, 1) + 1;
        if (arrived == GRID) {
            g_count = 0;
            __threadfence();
            g_sense = target;
        } else {
            while (g_sense != target) { }
        }
    }
    __syncthreads();
    __threadfence();   // acquire: order subsequent reads after the barrier
}

__device__ __forceinline__ float4 ldcs4(const float4* p)
{
    float4 v;
    asm volatile("ld.global.cs.v4.f32 {%0,%1,%2,%3}, [%4];"
                 : "=f"(v.x), "=f"(v.y), "=f"(v.z), "=f"(v.w)
                 : "l"(p));
    return v;
}

__global__ void __launch_bounds__(256, 2) fused_kernel(
    const float4* __restrict__ g1, const float4* __restrict__ g2,
    const float4* __restrict__ w1, const float4* __restrict__ w2,
    float* __restrict__ out)
{
    const int tid  = threadIdx.x;
    const int wid  = tid >> 5;
    const int lane = tid & 31;
    const int head = (blockIdx.x >= BPH) ? 1 : 0;
    const int bh   = blockIdx.x - head * BPH; // block index within head

    const float4* __restrict__ G = head ? g2 : g1;
    const float4* __restrict__ W = head ? w2 : w1;
    float* __restrict__ lg = g_logits + head * SEQ;

    // ---- weights live in registers for the whole kernel (32 regs/lane) ----
    float4 w[8];
#pragma unroll
    for (int i = 0; i < 8; i++) w[i] = __ldg(&W[lane + i * 32]);

    // ---------------- Phase A: logits + block-local max -------------------
    const int wIdx = bh * WPB + wid; // warp index within head, 0..WPH-1
    float wmax = -INFINITY;

    for (int row = wIdx; row < SEQ; row += WPH) {
        const float4* __restrict__ gr = G + (size_t)row * D4;
        float4 a[8];
#pragma unroll
        for (int i = 0; i < 8; i++) a[i] = ldcs4(&gr[lane + i * 32]);

        float acc = 0.0f;
#pragma unroll
        for (int i = 0; i < 8; i++) {
            acc = fmaf(a[i].x, w[i].x, acc);
            acc = fmaf(a[i].y, w[i].y, acc);
            acc = fmaf(a[i].z, w[i].z, acc);
            acc = fmaf(a[i].w, w[i].w, acc);
        }
#pragma unroll
        for (int o = 16; o > 0; o >>= 1)
            acc += __shfl_down_sync(0xffffffffu, acc, o);

        if (lane == 0) {
            lg[row] = acc;
            wmax = fmaxf(wmax, acc);
        }
    }

    __shared__ float s_part[WPB];
    __shared__ float s_m, s_s;
    if (lane == 0) s_part[wid] = wmax;
    __syncthreads();
    if (tid == 0) {
        float bm = -INFINITY;
#pragma unroll
        for (int i = 0; i < WPB; i++) bm = fmaxf(bm, s_part[i]);
        g_blockmax[blockIdx.x] = bm;
    }

    grid_barrier(1);

    // ---------------- Phase B: global max + partial exp-sum ----------------
    if (tid < 32) {
        float m = -INFINITY;
        for (int j = lane; j < BPH; j += 32)
            m = fmaxf(m, g_blockmax[head * BPH + j]);
#pragma unroll
        for (int o = 16; o > 0; o >>= 1)
            m = fmaxf(m, __shfl_xor_sync(0xffffffffu, m, o));
        if (lane == 0) s_m = m;
    }
    __syncthreads();
    const float m = s_m;

    const int tIdx = bh * 256 + tid;      // 0 .. BPH*256-1 within head
    float psum = 0.0f;
    for (int i = tIdx; i < SEQ; i += BPH * 256)
        psum += __expf(lg[i] - m);
#pragma unroll
    for (int o = 16; o > 0; o >>= 1)
        psum += __shfl_down_sync(0xffffffffu, psum, o);
    if (lane == 0) s_part[wid] = psum;
    __syncthreads();
    if (tid == 0) {
        float s = 0.0f;
#pragma unroll
        for (int i = 0; i < WPB; i++) s += s_part[i];
        g_blocksum[blockIdx.x] = s;
    }

    grid_barrier(0);

    // ---------------- Phase C: global sum + normalize ----------------------
    if (tid < 32) {
        float s = 0.0f;
        for (int j = lane; j < BPH; j += 32)
            s += g_blocksum[head * BPH + j];
#pragma unroll
        for (int o = 16; o > 0; o >>= 1)
            s += __shfl_xor_sync(0xffffffffu, s, o);
        if (lane == 0) s_s = s;
    }
    __syncthreads();
    const float inv = 1.0f / s_s;

    float* __restrict__ oh = out + head * SEQ;
    for (int i = tIdx; i < SEQ; i += BPH * 256)
        oh[i] = __expf(lg[i] - m) * inv;
}

extern "C" void kernel_launch(void* const* d_in, const int* in_sizes, int n_in,
                              void* d_out, int out_size)
{
    const float4* g1 = (const float4*)d_in[0]; // G_M1 [SEQ, D]
    const float4* g2 = (const float4*)d_in[1]; // G_M2 [SEQ, D]
    const float4* w1 = (const float4*)d_in[2]; // wp1  [1, D]
    const float4* w2 = (const float4*)d_in[3]; // wp2  [1, D]
    float* out = (float*)d_out;                // [2, SEQ]

    fused_kernel<<<GRID, 256>>>(g1, g2, w1, w2, out);
}

// round 15
// speedup vs baseline: 1.0009x; 1.0009x over previous
#include <cuda_runtime.h>
#include <math.h>

#define SEQ   16384
#define D4    256           // 1024 floats = 256 float4 per row
#define GRID  296           // 2 blocks/SM on 148 SMs (GB300 has 152 -> headroom)
#define BPH   (GRID / 2)    // 148 blocks per head
#define WPB   8             // warps per block (256 threads)
#define WPH   (BPH * WPB)   // 1184 warps per head

__device__ float g_logits[2 * SEQ];
__device__ float g_blockmax[GRID];
__device__ float g_blocksum[GRID];
__device__ volatile unsigned g_sense; // zero-init; returns to 0 after 2 barriers
__device__ unsigned g_count;          // zero-init; self-resets

// Sense-reversing grid barrier. All GRID blocks must be resident (guaranteed
// by __launch_bounds__(256,2): <=128 regs/thread -> 2 blocks/SM).
// Called an EVEN number of times per launch so g_sense ends at 0 (replay-safe).
__device__ __forceinline__ void grid_barrier(unsigned target)
{
    __threadfence();   // make this thread's prior global writes visible
    __syncthreads();
    if (threadIdx.x == 0) {
        unsigned arrived = atomicAdd(&g_count, 1) + 1;
        if (arrived == GRID) {
            g_count = 0;
            __threadfence();
            g_sense = target;
        } else {
            while (g_sense != target) { }
        }
    }
    __syncthreads();
    __threadfence();   // acquire: order subsequent reads after the barrier
}

__device__ __forceinline__ float4 ldcs4(const float4* p)
{
    float4 v;
    asm volatile("ld.global.cs.v4.f32 {%0,%1,%2,%3}, [%4];"
                 : "=f"(v.x), "=f"(v.y), "=f"(v.z), "=f"(v.w)
                 : "l"(p));
    return v;
}

__global__ void __launch_bounds__(256, 2) fused_kernel(
    const float4* __restrict__ g1, const float4* __restrict__ g2,
    const float4* __restrict__ w1, const float4* __restrict__ w2,
    float* __restrict__ out)
{
    const int tid  = threadIdx.x;
    const int wid  = tid >> 5;
    const int lane = tid & 31;
    const int head = (blockIdx.x >= BPH) ? 1 : 0;
    const int bh   = blockIdx.x - head * BPH; // block index within head

    const float4* __restrict__ G = head ? g2 : g1;
    const float4* __restrict__ W = head ? w2 : w1;
    float* __restrict__ lg = g_logits + head * SEQ;

    // ---- weights live in registers for the whole kernel (32 regs/lane) ----
    float4 w[8];
#pragma unroll
    for (int i = 0; i < 8; i++) w[i] = __ldg(&W[lane + i * 32]);

    // ---------------- Phase A: logits + block-local max -------------------
    const int wIdx = bh * WPB + wid; // warp index within head, 0..WPH-1
    float wmax = -INFINITY;

    for (int row = wIdx; row < SEQ; row += WPH) {
        const float4* __restrict__ gr = G + (size_t)row * D4;
        float4 a[8];
#pragma unroll
        for (int i = 0; i < 8; i++) a[i] = ldcs4(&gr[lane + i * 32]);

        float acc = 0.0f;
#pragma unroll
        for (int i = 0; i < 8; i++) {
            acc = fmaf(a[i].x, w[i].x, acc);
            acc = fmaf(a[i].y, w[i].y, acc);
            acc = fmaf(a[i].z, w[i].z, acc);
            acc = fmaf(a[i].w, w[i].w, acc);
        }
#pragma unroll
        for (int o = 16; o > 0; o >>= 1)
            acc += __shfl_down_sync(0xffffffffu, acc, o);

        if (lane == 0) {
            lg[row] = acc;
            wmax = fmaxf(wmax, acc);
        }
    }

    __shared__ float s_part[WPB];
    __shared__ float s_m, s_s;
    if (lane == 0) s_part[wid] = wmax;
    __syncthreads();
    if (tid == 0) {
        float bm = -INFINITY;
#pragma unroll
        for (int i = 0; i < WPB; i++) bm = fmaxf(bm, s_part[i]);
        g_blockmax[blockIdx.x] = bm;
    }

    grid_barrier(1);

    // ---------------- Phase B: global max + partial exp-sum ----------------
    if (tid < 32) {
        float m = -INFINITY;
        for (int j = lane; j < BPH; j += 32)
            m = fmaxf(m, g_blockmax[head * BPH + j]);
#pragma unroll
        for (int o = 16; o > 0; o >>= 1)
            m = fmaxf(m, __shfl_xor_sync(0xffffffffu, m, o));
        if (lane == 0) s_m = m;
    }
    __syncthreads();
    const float m = s_m;

    const int tIdx = bh * 256 + tid;      // 0 .. BPH*256-1 within head
    float psum = 0.0f;
    for (int i = tIdx; i < SEQ; i += BPH * 256)
        psum += __expf(lg[i] - m);
#pragma unroll
    for (int o = 16; o > 0; o >>= 1)
        psum += __shfl_down_sync(0xffffffffu, psum, o);
    if (lane == 0) s_part[wid] = psum;
    __syncthreads();
    if (tid == 0) {
        float s = 0.0f;
#pragma unroll
        for (int i = 0; i < WPB; i++) s += s_part[i];
        g_blocksum[blockIdx.x] = s;
    }

    grid_barrier(0);

    // ---------------- Phase C: global sum + normalize ----------------------
    if (tid < 32) {
        float s = 0.0f;
        for (int j = lane; j < BPH; j += 32)
            s += g_blocksum[head * BPH + j];
#pragma unroll
        for (int o = 16; o > 0; o >>= 1)
            s += __shfl_xor_sync(0xffffffffu, s, o);
        if (lane == 0) s_s = s;
    }
    __syncthreads();
    const float inv = 1.0f / s_s;

    float* __restrict__ oh = out + head * SEQ;
    for (int i = tIdx; i < SEQ; i += BPH * 256)
        oh[i] = __expf(lg[i] - m) * inv;
}

extern "C" void kernel_launch(void* const* d_in, const int* in_sizes, int n_in,
                              void* d_out, int out_size)
{
    const float4* g1 = (const float4*)d_in[0]; // G_M1 [SEQ, D]
    const float4* g2 = (const float4*)d_in[1]; // G_M2 [SEQ, D]
    const float4* w1 = (const float4*)d_in[2]; // wp1  [1, D]
    const float4* w2 = (const float4*)d_in[3]; // wp2  [1, D]
    float* out = (float*)d_out;                // [2, SEQ]

    fused_kernel<<<GRID, 256>>>(g1, g2, w1, w2, out);
}

// round 16
// speedup vs baseline: 1.0239x; 1.0229x over previous
#include <cuda_runtime.h>
#include <math.h>

#define SEQ   16384
#define D4    256           // 1024 floats = 256 float4 per row
#define GRID  296           // 2 blocks/SM on 148 SMs (GB300 has 152 -> headroom)
#define BPH   (GRID / 2)    // 148 blocks per head
#define WPB   8             // warps per block (256 threads)
#define WPH   (BPH * WPB)   // 1184 warps per head

__device__ float g_logits[2 * SEQ];
__device__ float g_blockmax[GRID];
__device__ float g_blocksum[GRID];
__device__ volatile unsigned g_sense; // zero-init; returns to 0 after 2 barriers
__device__ unsigned g_count;          // zero-init; self-resets

// Sense-reversing grid barrier. All GRID blocks must be resident (guaranteed
// by __launch_bounds__(256,2): <=128 regs/thread -> 2 blocks/SM).
// Called an EVEN number of times per launch so g_sense ends at 0 (replay-safe).
__device__ __forceinline__ void grid_barrier(unsigned target)
{
    __threadfence();   // make this thread's prior global writes visible
    __syncthreads();
    if (threadIdx.x == 0) {
        unsigned arrived = atomicAdd(&g_count, 1) + 1;
        if (arrived == GRID) {
            g_count = 0;
            __threadfence();
            g_sense = target;
        } else {
            while (g_sense != target) { }
        }
    }
    __syncthreads();
    __threadfence();   // acquire: order subsequent reads after the barrier
}

__device__ __forceinline__ float4 ldcs4(const float4* p)
{
    float4 v;
    asm volatile("ld.global.cs.v4.f32 {%0,%1,%2,%3}, [%4];"
                 : "=f"(v.x), "=f"(v.y), "=f"(v.z), "=f"(v.w)
                 : "l"(p));
    return v;
}

__global__ void __launch_bounds__(256, 2) fused_kernel(
    const float4* __restrict__ g1, const float4* __restrict__ g2,
    const float4* __restrict__ w1, const float4* __restrict__ w2,
    float* __restrict__ out)
{
    const int tid  = threadIdx.x;
    const int wid  = tid >> 5;
    const int lane = tid & 31;
    const int head = (blockIdx.x >= BPH) ? 1 : 0;
    const int bh   = blockIdx.x - head * BPH; // block index within head

    const float4* __restrict__ G = head ? g2 : g1;
    const float4* __restrict__ W = head ? w2 : w1;
    float* __restrict__ lg = g_logits + head * SEQ;

    // ---- weights live in registers for the whole kernel (32 regs/lane) ----
    float4 w[8];
#pragma unroll
    for (int i = 0; i < 8; i++) w[i] = __ldg(&W[lane + i * 32]);

    // ---------------- Phase A: logits + block-local max -------------------
    const int wIdx = bh * WPB + wid; // warp index within head, 0..WPH-1
    float wmax = -INFINITY;

    for (int row = wIdx; row < SEQ; row += WPH) {
        const float4* __restrict__ gr = G + (size_t)row * D4;
        float4 a[8];
#pragma unroll
        for (int i = 0; i < 8; i++) a[i] = ldcs4(&gr[lane + i * 32]);

        float acc = 0.0f;
#pragma unroll
        for (int i = 0; i < 8; i++) {
            acc = fmaf(a[i].x, w[i].x, acc);
            acc = fmaf(a[i].y, w[i].y, acc);
            acc = fmaf(a[i].z, w[i].z, acc);
            acc = fmaf(a[i].w, w[i].w, acc);
        }
#pragma unroll
        for (int o = 16; o > 0; o >>= 1)
            acc += __shfl_down_sync(0xffffffffu, acc, o);

        if (lane == 0) {
            lg[row] = acc;
            wmax = fmaxf(wmax, acc);
        }
    }

    __shared__ float s_part[WPB];
    __shared__ float s_m, s_s;
    if (lane == 0) s_part[wid] = wmax;
    __syncthreads();
    if (tid == 0) {
        float bm = -INFINITY;
#pragma unroll
        for (int i = 0; i < WPB; i++) bm = fmaxf(bm, s_part[i]);
        g_blockmax[blockIdx.x] = bm;
    }

    grid_barrier(1);

    // ---------------- Phase B: global max + partial exp-sum ----------------
    if (tid < 32) {
        float m = -INFINITY;
        for (int j = lane; j < BPH; j += 32)
            m = fmaxf(m, g_blockmax[head * BPH + j]);
#pragma unroll
        for (int o = 16; o > 0; o >>= 1)
            m = fmaxf(m, __shfl_xor_sync(0xffffffffu, m, o));
        if (lane == 0) s_m = m;
    }
    __syncthreads();
    const float m = s_m;

    const int tIdx = bh * 256 + tid;      // 0 .. BPH*256-1 within head
    float psum = 0.0f;
    for (int i = tIdx; i < SEQ; i += BPH * 256)
        psum += __expf(lg[i] - m);
#pragma unroll
    for (int o = 16; o > 0; o >>= 1)
        psum += __shfl_down_sync(0xffffffffu, psum, o);
    if (lane == 0) s_part[wid] = psum;
    __syncthreads();
    if (tid == 0) {
        float s = 0.0f;
#pragma unroll
        for (int i = 0; i < WPB; i++) s += s_part[i];
        g_blocksum[blockIdx.x] = s;
    }

    grid_barrier(0);

    // ---------------- Phase C: global sum + normalize ----------------------
    if (tid < 32) {
        float s = 0.0f;
        for (int j = lane; j < BPH; j += 32)
            s += g_blocksum[head * BPH + j];
#pragma unroll
        for (int o = 16; o > 0; o >>= 1)
            s += __shfl_xor_sync(0xffffffffu, s, o);
        if (lane == 0) s_s = s;
    }
    __syncthreads();
    const float inv = 1.0f / s_s;

    float* __restrict__ oh = out + head * SEQ;
    for (int i = tIdx; i < SEQ; i += BPH * 256)
        oh[i] = __expf(lg[i] - m) * inv;
}

extern "C" void kernel_launch(void* const* d_in, const int* in_sizes, int n_in,
                              void* d_out, int out_size)
{
    const float4* g1 = (const float4*)d_in[0]; // G_M1 [SEQ, D]
    const float4* g2 = (const float4*)d_in[1]; // G_M2 [SEQ, D]
    const float4* w1 = (const float4*)d_in[2]; // wp1  [1, D]
    const float4* w2 = (const float4*)d_in[3]; // wp2  [1, D]
    float* out = (float*)d_out;                // [2, SEQ]

    fused_kernel<<<GRID, 256>>>(g1, g2, w1, w2, out);
}

// round 17
// speedup vs baseline: 1.0327x; 1.0087x over previous
#include <cuda_runtime.h>
#include <math.h>

#define SEQ   16384
#define D4    256           // 1024 floats = 256 float4 per row
#define GRID  296           // 2 blocks/SM on 148 SMs (GB300 has 152 -> headroom)
#define BPH   (GRID / 2)    // 148 blocks per head
#define WPB   8             // warps per block (256 threads)
#define WPH   (BPH * WPB)   // 1184 warps per head

__device__ float g_logits[2 * SEQ];
__device__ float g_blockmax[GRID];
__device__ float g_blocksum[GRID];
__device__ volatile unsigned g_sense; // zero-init; returns to 0 after 2 barriers
__device__ unsigned g_count;          // zero-init; self-resets

// Sense-reversing grid barrier. All GRID blocks must be resident (guaranteed
// by __launch_bounds__(256,2): <=128 regs/thread -> 2 blocks/SM).
// Called an EVEN number of times per launch so g_sense ends at 0 (replay-safe).
__device__ __forceinline__ void grid_barrier(unsigned target)
{
    __threadfence();   // make this thread's prior global writes visible
    __syncthreads();
    if (threadIdx.x == 0) {
        unsigned arrived = atomicAdd(&g_count, 1) + 1;
        if (arrived == GRID) {
            g_count = 0;
            __threadfence();
            g_sense = target;
        } else {
            while (g_sense != target) { }
        }
    }
    __syncthreads();
    __threadfence();   // acquire: order subsequent reads after the barrier
}

__device__ __forceinline__ float4 ldcs4(const float4* p)
{
    float4 v;
    asm volatile("ld.global.cs.v4.f32 {%0,%1,%2,%3}, [%4];"
                 : "=f"(v.x), "=f"(v.y), "=f"(v.z), "=f"(v.w)
                 : "l"(p));
    return v;
}

__global__ void __launch_bounds__(256, 2) fused_kernel(
    const float4* __restrict__ g1, const float4* __restrict__ g2,
    const float4* __restrict__ w1, const float4* __restrict__ w2,
    float* __restrict__ out)
{
    const int tid  = threadIdx.x;
    const int wid  = tid >> 5;
    const int lane = tid & 31;
    const int head = (blockIdx.x >= BPH) ? 1 : 0;
    const int bh   = blockIdx.x - head * BPH; // block index within head

    const float4* __restrict__ G = head ? g2 : g1;
    const float4* __restrict__ W = head ? w2 : w1;
    float* __restrict__ lg = g_logits + head * SEQ;

    // ---- weights live in registers for the whole kernel (32 regs/lane) ----
    float4 w[8];
#pragma unroll
    for (int i = 0; i < 8; i++) w[i] = __ldg(&W[lane + i * 32]);

    // ---------------- Phase A: logits + block-local max -------------------
    const int wIdx = bh * WPB + wid; // warp index within head, 0..WPH-1
    float wmax = -INFINITY;

    for (int row = wIdx; row < SEQ; row += WPH) {
        const float4* __restrict__ gr = G + (size_t)row * D4;
        float4 a[8];
#pragma unroll
        for (int i = 0; i < 8; i++) a[i] = ldcs4(&gr[lane + i * 32]);

        float acc = 0.0f;
#pragma unroll
        for (int i = 0; i < 8; i++) {
            acc = fmaf(a[i].x, w[i].x, acc);
            acc = fmaf(a[i].y, w[i].y, acc);
            acc = fmaf(a[i].z, w[i].z, acc);
            acc = fmaf(a[i].w, w[i].w, acc);
        }
#pragma unroll
        for (int o = 16; o > 0; o >>= 1)
            acc += __shfl_down_sync(0xffffffffu, acc, o);

        if (lane == 0) {
            lg[row] = acc;
            wmax = fmaxf(wmax, acc);
        }
    }

    __shared__ float s_part[WPB];
    __shared__ float s_m, s_s;
    if (lane == 0) s_part[wid] = wmax;
    __syncthreads();
    if (tid == 0) {
        float bm = -INFINITY;
#pragma unroll
        for (int i = 0; i < WPB; i++) bm = fmaxf(bm, s_part[i]);
        g_blockmax[blockIdx.x] = bm;
    }

    grid_barrier(1);

    // ---------------- Phase B: global max + partial exp-sum ----------------
    if (tid < 32) {
        float m = -INFINITY;
        for (int j = lane; j < BPH; j += 32)
            m = fmaxf(m, g_blockmax[head * BPH + j]);
#pragma unroll
        for (int o = 16; o > 0; o >>= 1)
            m = fmaxf(m, __shfl_xor_sync(0xffffffffu, m, o));
        if (lane == 0) s_m = m;
    }
    __syncthreads();
    const float m = s_m;

    const int tIdx = bh * 256 + tid;      // 0 .. BPH*256-1 within head
    float psum = 0.0f;
    for (int i = tIdx; i < SEQ; i += BPH * 256)
        psum += __expf(lg[i] - m);
#pragma unroll
    for (int o = 16; o > 0; o >>= 1)
        psum += __shfl_down_sync(0xffffffffu, psum, o);
    if (lane == 0) s_part[wid] = psum;
    __syncthreads();
    if (tid == 0) {
        float s = 0.0f;
#pragma unroll
        for (int i = 0; i < WPB; i++) s += s_part[i];
        g_blocksum[blockIdx.x] = s;
    }

    grid_barrier(0);

    // ---------------- Phase C: global sum + normalize ----------------------
    if (tid < 32) {
        float s = 0.0f;
        for (int j = lane; j < BPH; j += 32)
            s += g_blocksum[head * BPH + j];
#pragma unroll
        for (int o = 16; o > 0; o >>= 1)
            s += __shfl_xor_sync(0xffffffffu, s, o);
        if (lane == 0) s_s = s;
    }
    __syncthreads();
    const float inv = 1.0f / s_s;

    float* __restrict__ oh = out + head * SEQ;
    for (int i = tIdx; i < SEQ; i += BPH * 256)
        oh[i] = __expf(lg[i] - m) * inv;
}

extern "C" void kernel_launch(void* const* d_in, const int* in_sizes, int n_in,
                              void* d_out, int out_size)
{
    const float4* g1 = (const float4*)d_in[0]; // G_M1 [SEQ, D]
    const float4* g2 = (const float4*)d_in[1]; // G_M2 [SEQ, D]
    const float4* w1 = (const float4*)d_in[2]; // wp1  [1, D]
    const float4* w2 = (const float4*)d_in[3]; // wp2  [1, D]
    float* out = (float*)d_out;                // [2, SEQ]

    fused_kernel<<<GRID, 256>>>(g1, g2, w1, w2, out);
}